// round 2
// baseline (speedup 1.0000x reference)
#include <cuda_runtime.h>
#include <math.h>

typedef unsigned long long ull;

#define T_  256
#define B_  256
#define I_  512
#define H_  512
#define G3  1536

// ---------------- scratch (device globals: allocation-free rule) --------------
__device__ float g_gi[(long long)T_ * B_ * G3];    // 402 MB: per-timestep input projections
__device__ float g_outs[(long long)T_ * B_ * H_];  // 134 MB: pre-LN hidden states (= h history)

// ---------------- packed f32x2 helpers (Blackwell FFMA2) ---------------------
#define USE_F32X2 1

__device__ __forceinline__ ull pk(float lo, float hi) {
    ull r;
    asm("mov.b64 %0, {%1, %2};" : "=l"(r) : "f"(lo), "f"(hi));
    return r;
}
__device__ __forceinline__ void upk(ull v, float& lo, float& hi) {
    asm("mov.b64 {%0, %1}, %2;" : "=f"(lo), "=f"(hi) : "l"(v));
}
__device__ __forceinline__ void ffma2(ull& d, ull a, ull b) {
#if USE_F32X2
    asm("fma.rn.f32x2 %0, %1, %2, %0;" : "+l"(d) : "l"(a), "l"(b));
#else
    float dl, dh, al, ah, bl, bh;
    upk(d, dl, dh); upk(a, al, ah); upk(b, bl, bh);
    d = pk(fmaf(al, bl, dl), fmaf(ah, bh, dh));
#endif
}

// =============================================================================
// Kernel 1: gi = x @ W_ih^T + b_ih     (M=65536, N=1536, K=512), fp32, FFMA2
// BM=128, BN=128, BK=16, 256 threads, 8x8 microtile.
// =============================================================================
__global__ void __launch_bounds__(256) gemm_gi_kernel(
    const float* __restrict__ X,     // [M, 512]
    const float* __restrict__ Wih,   // [1536, 512]
    const float* __restrict__ bih)   // [1536]
{
    __shared__ float As[16][132];  // [k][m], padded stride 132 (16B-aligned rows)
    __shared__ float Bs[16][132];  // [k][n]

    const int tid  = threadIdx.x;
    const int m0   = blockIdx.y * 128;
    const int n0   = blockIdx.x * 128;
    const int trow = tid >> 4;   // 0..15
    const int tcol = tid & 15;   // 0..15

    ull acc[4][8];
    #pragma unroll
    for (int p = 0; p < 4; p++)
        #pragma unroll
        for (int j = 0; j < 8; j++) acc[p][j] = 0ull;

    for (int kb = 0; kb < 512; kb += 16) {
        __syncthreads();
        #pragma unroll
        for (int l = 0; l < 2; l++) {
            int idx = tid + l * 256;          // 0..511
            int r   = idx >> 2;               // 0..127
            int c4  = idx & 3;                // 0..3
            float4 a = *(const float4*)&X[(long long)(m0 + r) * 512 + kb + c4 * 4];
            As[c4 * 4 + 0][r] = a.x; As[c4 * 4 + 1][r] = a.y;
            As[c4 * 4 + 2][r] = a.z; As[c4 * 4 + 3][r] = a.w;
            float4 b = *(const float4*)&Wih[(long long)(n0 + r) * 512 + kb + c4 * 4];
            Bs[c4 * 4 + 0][r] = b.x; Bs[c4 * 4 + 1][r] = b.y;
            Bs[c4 * 4 + 2][r] = b.z; Bs[c4 * 4 + 3][r] = b.w;
        }
        __syncthreads();
        #pragma unroll
        for (int kk = 0; kk < 16; kk++) {
            ulonglong2 a01 = *(const ulonglong2*)&As[kk][trow * 8];
            ulonglong2 a23 = *(const ulonglong2*)&As[kk][trow * 8 + 4];
            float4 b0 = *(const float4*)&Bs[kk][tcol * 8];
            float4 b1 = *(const float4*)&Bs[kk][tcol * 8 + 4];
            ull a2[4] = { a01.x, a01.y, a23.x, a23.y };
            float bv[8] = { b0.x, b0.y, b0.z, b0.w, b1.x, b1.y, b1.z, b1.w };
            #pragma unroll
            for (int j = 0; j < 8; j++) {
                ull b2 = pk(bv[j], bv[j]);
                #pragma unroll
                for (int p = 0; p < 4; p++) ffma2(acc[p][j], a2[p], b2);
            }
        }
    }

    // epilogue: + b_ih, store
    float bias[8];
    #pragma unroll
    for (int j = 0; j < 8; j++) bias[j] = bih[n0 + tcol * 8 + j];

    #pragma unroll
    for (int p = 0; p < 4; p++) {
        float lo[8], hi[8];
        #pragma unroll
        for (int j = 0; j < 8; j++) upk(acc[p][j], lo[j], hi[j]);
        int mA = m0 + trow * 8 + 2 * p;
        int mB = mA + 1;
        float4 vA0 = { lo[0] + bias[0], lo[1] + bias[1], lo[2] + bias[2], lo[3] + bias[3] };
        float4 vA1 = { lo[4] + bias[4], lo[5] + bias[5], lo[6] + bias[6], lo[7] + bias[7] };
        float4 vB0 = { hi[0] + bias[0], hi[1] + bias[1], hi[2] + bias[2], hi[3] + bias[3] };
        float4 vB1 = { hi[4] + bias[4], hi[5] + bias[5], hi[6] + bias[6], hi[7] + bias[7] };
        float* oA = &g_gi[(long long)mA * G3 + n0 + tcol * 8];
        float* oB = &g_gi[(long long)mB * G3 + n0 + tcol * 8];
        *(float4*)(oA)     = vA0;  *(float4*)(oA + 4) = vA1;
        *(float4*)(oB)     = vB0;  *(float4*)(oB + 4) = vB1;
    }
}

// =============================================================================
// Kernel 2: one GRU timestep (fused gemm + gates), fp32 FFMA2.
// grid = 128 blocks (each owns NJ=4 columns j of H), 256 threads.
// Thread tile: 2 rows x (2 j x 3 gates).  W_hh slice duplicated-packed in SMEM,
// h tiles (masked) double-buffered in SMEM.
// =============================================================================
#define NJ 4
#define HS_STRIDE 258            // 2-way STS conflict, conflict-free LDS.64
#define HS_BUF    (32 * HS_STRIDE)              // 8256 floats
#define SM_HS     (NJ * 512 * 8)                // Wp2: 16384 floats
#define SM_OSH    (SM_HS + 2 * HS_BUF)          // 16384+16512 = 32896
#define SM_MSH    (SM_OSH + 1024)               // 33920
#define STEP_SMEM_FLOATS (SM_MSH + 256)         // 34176
#define STEP_SMEM_BYTES  (STEP_SMEM_FLOATS * 4) // 136704 B

__global__ void __launch_bounds__(256, 1) gru_step_kernel(
    int t,
    const float* __restrict__ rnn,     // [B,H] initial hidden
    const float* __restrict__ masks,   // [T,B]
    const float* __restrict__ Whh,     // [1536,512]
    const float* __restrict__ bhh)     // [1536]
{
    extern __shared__ float sm[];
    float* Wp2 = sm;            // [jl][k][g-dup pairs, 8 floats]
    float* hs0 = sm + SM_HS;    // double buffer, each [32][HS_STRIDE]
    float* osh = sm + SM_OSH;   // [256][4]
    float* msh = sm + SM_MSH;   // [256]

    const float* prev   = (t == 0) ? rnn : (g_outs + (long long)(t - 1) * B_ * H_);
    const float* mask_t = masks + (long long)t * B_;
    const float* gi_t   = g_gi + (long long)t * B_ * G3;
    float*       out_t  = g_outs + (long long)t * B_ * H_;

    const int tid = threadIdx.x;
    const int j0  = blockIdx.x * NJ;
    const int rg  = tid & 127;       // row group
    const int jp  = tid >> 7;        // 0..1 -> j pair  (uniform per warp)
    const int r0  = rg * 2;

    msh[tid] = mask_t[tid];

    // W_hh slice, duplicated-packed: Wp2[(jl*512+k)*8 + g*2 + {0,1}] = W[g*512+j0+jl][k]
    for (int e = tid; e < NJ * 512 * 3; e += 256) {
        int jl = e / 1536;
        int r2 = e - jl * 1536;
        int k  = r2 / 3;
        int g  = r2 - k * 3;
        float v = Whh[(long long)(g * 512 + j0 + jl) * 512 + k];
        int base = (jl * 512 + k) * 8 + g * 2;
        Wp2[base] = v; Wp2[base + 1] = v;
    }

    float4 ld[8];
    auto LDCHUNK = [&](int kb) {
        #pragma unroll
        for (int i = 0; i < 8; i++) {
            int e = tid + i * 256;
            int c = e & 7;
            int r = e >> 3;
            ld[i] = *(const float4*)&prev[(long long)r * 512 + kb + c * 4];
        }
    };
    auto STCHUNK = [&](float* buf) {
        #pragma unroll
        for (int i = 0; i < 8; i++) {
            int e = tid + i * 256;
            int c = e & 7;
            int r = e >> 3;
            float m = msh[r];
            buf[(c * 4 + 0) * HS_STRIDE + r] = ld[i].x * m;
            buf[(c * 4 + 1) * HS_STRIDE + r] = ld[i].y * m;
            buf[(c * 4 + 2) * HS_STRIDE + r] = ld[i].z * m;
            buf[(c * 4 + 3) * HS_STRIDE + r] = ld[i].w * m;
        }
    };

    LDCHUNK(0);
    __syncthreads();          // msh + Wp2 ready
    STCHUNK(hs0);
    __syncthreads();

    ull acc[6] = {0ull, 0ull, 0ull, 0ull, 0ull, 0ull};  // [jj][gate]
    float hj[4];              // masked h at own columns: [jj][row i]

    for (int ci = 0; ci < 16; ci++) {
        const int kb = ci * 32;
        float* buf = hs0 + (ci & 1) * HS_BUF;
        if (ci < 15) LDCHUNK(kb + 32);     // prefetch next chunk (latency overlap)

        if (j0 >= kb && j0 < kb + 32) {    // grab masked h at this block's columns
            #pragma unroll
            for (int jj = 0; jj < 2; jj++) {
                int jl = jp * 2 + jj;
                hj[jj * 2 + 0] = buf[(j0 + jl - kb) * HS_STRIDE + r0];
                hj[jj * 2 + 1] = buf[(j0 + jl - kb) * HS_STRIDE + r0 + 1];
            }
        }

        #pragma unroll
        for (int kk = 0; kk < 32; kk++) {
            ull h2 = *(const ull*)&buf[kk * HS_STRIDE + r0];   // rows (r0, r0+1)
            #pragma unroll
            for (int jj = 0; jj < 2; jj++) {
                int jl = jp * 2 + jj;
                const float* wb = &Wp2[(jl * 512 + kb + kk) * 8];
                ulonglong2 w01 = *(const ulonglong2*)wb;   // {g0 dup, g1 dup}
                ull        w2  = *(const ull*)(wb + 4);    // g2 dup
                ffma2(acc[jj * 3 + 0], h2, w01.x);
                ffma2(acc[jj * 3 + 1], h2, w01.y);
                ffma2(acc[jj * 3 + 2], h2, w2);
            }
        }
        __syncthreads();
        if (ci < 15) { STCHUNK(hs0 + ((ci + 1) & 1) * HS_BUF); __syncthreads(); }
    }

    // ---------------- gates epilogue ----------------
    #pragma unroll
    for (int jj = 0; jj < 2; jj++) {
        int jl = jp * 2 + jj;
        int j  = j0 + jl;
        float ghr[2], ghz[2], ghn[2];
        upk(acc[jj * 3 + 0], ghr[0], ghr[1]);
        upk(acc[jj * 3 + 1], ghz[0], ghz[1]);
        upk(acc[jj * 3 + 2], ghn[0], ghn[1]);
        float br = bhh[j], bz = bhh[512 + j], bn = bhh[1024 + j];
        #pragma unroll
        for (int i = 0; i < 2; i++) {
            int r = r0 + i;
            float ir  = gi_t[(long long)r * G3 + j];
            float iz  = gi_t[(long long)r * G3 + 512 + j];
            float in_ = gi_t[(long long)r * G3 + 1024 + j];
            float rr = 1.0f / (1.0f + __expf(-(ir + ghr[i] + br)));
            float zz = 1.0f / (1.0f + __expf(-(iz + ghz[i] + bz)));
            float nn = tanhf(in_ + rr * (ghn[i] + bn));
            float hnew = (1.0f - zz) * nn + zz * hj[jj * 2 + i];
            osh[r * 4 + jl] = hnew;
        }
    }
    __syncthreads();

    // coalesced-ish store: one float4 (this block's 4 columns) per row
    {
        int r = tid;
        float4 v = *(const float4*)&osh[r * 4];
        *(float4*)&out_t[(long long)r * 512 + j0] = v;
    }
}

// =============================================================================
// Kernel 3: LayerNorm over g_outs -> y in d_out; also copy hT (raw outs[T-1]).
// One warp per row (512 floats). grid = 65536/8 blocks of 256 threads.
// =============================================================================
__global__ void __launch_bounds__(256) ln_kernel(
    const float* __restrict__ lnw,
    const float* __restrict__ lnb,
    float* __restrict__ out,
    int write_hT)
{
    const int row  = blockIdx.x * 8 + (threadIdx.x >> 5);
    const int lane = threadIdx.x & 31;
    const float4* p4 = (const float4*)(g_outs + (long long)row * 512);

    float4 v[4];
    float s = 0.0f, sq = 0.0f;
    #pragma unroll
    for (int i = 0; i < 4; i++) {
        v[i] = p4[lane + 32 * i];
        s += v[i].x + v[i].y + v[i].z + v[i].w;
        sq = fmaf(v[i].x, v[i].x, sq);
        sq = fmaf(v[i].y, v[i].y, sq);
        sq = fmaf(v[i].z, v[i].z, sq);
        sq = fmaf(v[i].w, v[i].w, sq);
    }
    #pragma unroll
    for (int off = 16; off > 0; off >>= 1) {
        s  += __shfl_xor_sync(0xFFFFFFFFu, s,  off);
        sq += __shfl_xor_sync(0xFFFFFFFFu, sq, off);
    }
    const float mean = s * (1.0f / 512.0f);
    const float var  = sq * (1.0f / 512.0f) - mean * mean;
    const float rstd = rsqrtf(var + 1e-5f);

    float4* o4 = (float4*)out + (long long)row * 128;
    const float4* w4 = (const float4*)lnw;
    const float4* b4 = (const float4*)lnb;
    const bool isLast = (row >= 255 * 256) && write_hT;
    float4* h4 = (float4*)(out + (long long)T_ * B_ * H_) + (long long)(row - 255 * 256) * 128;

    #pragma unroll
    for (int i = 0; i < 4; i++) {
        int idx = lane + 32 * i;
        float4 w = w4[idx], b = b4[idx];
        float4 y;
        y.x = (v[i].x - mean) * rstd * w.x + b.x;
        y.y = (v[i].y - mean) * rstd * w.y + b.y;
        y.z = (v[i].z - mean) * rstd * w.z + b.z;
        y.w = (v[i].w - mean) * rstd * w.w + b.w;
        o4[idx] = y;
        if (isLast) h4[idx] = v[i];
    }
}

// =============================================================================
extern "C" void kernel_launch(void* const* d_in, const int* in_sizes, int n_in,
                              void* d_out, int out_size)
{
    const float* x     = (const float*)d_in[0];  // (T,B,I)
    const float* rnn   = (const float*)d_in[1];  // (1,B,H)
    const float* masks = (const float*)d_in[2];  // (T,B,1)
    const float* Wih   = (const float*)d_in[3];  // (3H,I)
    const float* Whh   = (const float*)d_in[4];  // (3H,H)
    const float* bih   = (const float*)d_in[5];  // (3H)
    const float* bhh   = (const float*)d_in[6];  // (3H)
    const float* lnw   = (const float*)d_in[7];  // (H)
    const float* lnb   = (const float*)d_in[8];  // (H)
    float* out = (float*)d_out;

    (void)in_sizes; (void)n_in;

    cudaFuncSetAttribute(gru_step_kernel,
                         cudaFuncAttributeMaxDynamicSharedMemorySize, STEP_SMEM_BYTES);

    // 1) input projections for all timesteps
    gemm_gi_kernel<<<dim3(12, 512), 256>>>(x, Wih, bih);

    // 2) sequential recurrence
    for (int t = 0; t < T_; t++)
        gru_step_kernel<<<128, 256, STEP_SMEM_BYTES>>>(t, rnn, masks, Whh, bhh);

    // 3) LayerNorm + hT copy
    const int write_hT = (out_size >= T_ * B_ * H_ + B_ * H_) ? 1 : 0;
    ln_kernel<<<(T_ * B_) / 8, 256>>>(lnw, lnb, out, write_hT);
}

// round 3
// speedup vs baseline: 1.6807x; 1.6807x over previous
#include <cuda_runtime.h>
#include <math.h>

typedef unsigned long long ull;

#define T_  256
#define B_  256
#define I_  512
#define H_  512
#define G3  1536

// ---------------- scratch (device globals: allocation-free rule) --------------
__device__ float g_gi[(long long)T_ * B_ * G3];    // 402 MB: per-timestep input projections
__device__ float g_outs[(long long)T_ * B_ * H_];  // 67 MB: pre-LN hidden states (= h history)

// ---------------- packed f32x2 helpers (Blackwell FFMA2) ---------------------
__device__ __forceinline__ ull pk(float lo, float hi) {
    ull r;
    asm("mov.b64 %0, {%1, %2};" : "=l"(r) : "f"(lo), "f"(hi));
    return r;
}
__device__ __forceinline__ void upk(ull v, float& lo, float& hi) {
    asm("mov.b64 {%0, %1}, %2;" : "=f"(lo), "=f"(hi) : "l"(v));
}
__device__ __forceinline__ void ffma2(ull& d, ull a, ull b) {
    asm("fma.rn.f32x2 %0, %1, %2, %0;" : "+l"(d) : "l"(a), "l"(b));
}

// ---------------- cp.async helpers -------------------------------------------
__device__ __forceinline__ unsigned smaddr(const void* p) {
    return (unsigned)__cvta_generic_to_shared(p);
}
__device__ __forceinline__ void cpasync16(unsigned dst, const void* src) {
    asm volatile("cp.async.cg.shared.global [%0], [%1], 16;" :: "r"(dst), "l"(src));
}
__device__ __forceinline__ void cp_commit() {
    asm volatile("cp.async.commit_group;");
}
template<int N> __device__ __forceinline__ void cp_wait() {
    asm volatile("cp.async.wait_group %0;" :: "n"(N));
}

// =============================================================================
// Kernel 1: gi = x @ W_ih^T + b_ih     (M=65536, N=1536, K=512), fp32, FFMA2
// =============================================================================
__global__ void __launch_bounds__(256) gemm_gi_kernel(
    const float* __restrict__ X,     // [M, 512]
    const float* __restrict__ Wih,   // [1536, 512]
    const float* __restrict__ bih)   // [1536]
{
    __shared__ float As[16][132];
    __shared__ float Bs[16][132];

    const int tid  = threadIdx.x;
    const int m0   = blockIdx.y * 128;
    const int n0   = blockIdx.x * 128;
    const int trow = tid >> 4;
    const int tcol = tid & 15;

    ull acc[4][8];
    #pragma unroll
    for (int p = 0; p < 4; p++)
        #pragma unroll
        for (int j = 0; j < 8; j++) acc[p][j] = 0ull;

    for (int kb = 0; kb < 512; kb += 16) {
        __syncthreads();
        #pragma unroll
        for (int l = 0; l < 2; l++) {
            int idx = tid + l * 256;
            int r   = idx >> 2;
            int c4  = idx & 3;
            float4 a = *(const float4*)&X[(long long)(m0 + r) * 512 + kb + c4 * 4];
            As[c4 * 4 + 0][r] = a.x; As[c4 * 4 + 1][r] = a.y;
            As[c4 * 4 + 2][r] = a.z; As[c4 * 4 + 3][r] = a.w;
            float4 b = *(const float4*)&Wih[(long long)(n0 + r) * 512 + kb + c4 * 4];
            Bs[c4 * 4 + 0][r] = b.x; Bs[c4 * 4 + 1][r] = b.y;
            Bs[c4 * 4 + 2][r] = b.z; Bs[c4 * 4 + 3][r] = b.w;
        }
        __syncthreads();
        #pragma unroll
        for (int kk = 0; kk < 16; kk++) {
            ulonglong2 a01 = *(const ulonglong2*)&As[kk][trow * 8];
            ulonglong2 a23 = *(const ulonglong2*)&As[kk][trow * 8 + 4];
            float4 b0 = *(const float4*)&Bs[kk][tcol * 8];
            float4 b1 = *(const float4*)&Bs[kk][tcol * 8 + 4];
            ull a2[4] = { a01.x, a01.y, a23.x, a23.y };
            float bv[8] = { b0.x, b0.y, b0.z, b0.w, b1.x, b1.y, b1.z, b1.w };
            #pragma unroll
            for (int j = 0; j < 8; j++) {
                ull b2 = pk(bv[j], bv[j]);
                #pragma unroll
                for (int p = 0; p < 4; p++) ffma2(acc[p][j], a2[p], b2);
            }
        }
    }

    float bias[8];
    #pragma unroll
    for (int j = 0; j < 8; j++) bias[j] = bih[n0 + tcol * 8 + j];

    #pragma unroll
    for (int p = 0; p < 4; p++) {
        float lo[8], hi[8];
        #pragma unroll
        for (int j = 0; j < 8; j++) upk(acc[p][j], lo[j], hi[j]);
        int mA = m0 + trow * 8 + 2 * p;
        int mB = mA + 1;
        float4 vA0 = { lo[0] + bias[0], lo[1] + bias[1], lo[2] + bias[2], lo[3] + bias[3] };
        float4 vA1 = { lo[4] + bias[4], lo[5] + bias[5], lo[6] + bias[6], lo[7] + bias[7] };
        float4 vB0 = { hi[0] + bias[0], hi[1] + bias[1], hi[2] + bias[2], hi[3] + bias[3] };
        float4 vB1 = { hi[4] + bias[4], hi[5] + bias[5], hi[6] + bias[6], hi[7] + bias[7] };
        float* oA = &g_gi[(long long)mA * G3 + n0 + tcol * 8];
        float* oB = &g_gi[(long long)mB * G3 + n0 + tcol * 8];
        *(float4*)(oA)     = vA0;  *(float4*)(oA + 4) = vA1;
        *(float4*)(oB)     = vB0;  *(float4*)(oB + 4) = vB1;
    }
}

// =============================================================================
// Kernel 2 (v2): one GRU timestep.
//  GEMM gh_raw = h_prev @ W_hh^T on a 64x48 tile (16 j-cols x 3 gates),
//  mask applied in epilogue:  gh = m[r]*gh_raw + b_hh.
//  k-parity f32x2 packing: A[row][k], B[c][k] natural layouts, cp.async staged.
//  grid (32, 4) = 128 blocks, 256 threads, microtile 4 rows x 3 gates (1 j).
// =============================================================================
#define BK   32
#define PADK 36   // row stride in floats (keeps 16B align, breaks bank conflicts)

__global__ void __launch_bounds__(256, 1) gru_step_kernel(
    int t,
    const float* __restrict__ rnn,     // [B,H] initial hidden
    const float* __restrict__ masks,   // [T,B]
    const float* __restrict__ Whh,     // [1536,512]
    const float* __restrict__ bhh)     // [1536]
{
    __shared__ float As[2][64 * PADK];   // [buf][row][k]
    __shared__ float Bs[2][48 * PADK];   // [buf][c=g*16+jj][k]

    const int tid = threadIdx.x;
    const int tc  = tid & 15;        // j within block
    const int tr  = tid >> 4;        // row group (0..15), 4 rows each
    const int j0  = blockIdx.x * 16;
    const int m0  = blockIdx.y * 64;
    const int j   = j0 + tc;

    const float* prev = (t == 0) ? rnn : (g_outs + (long long)(t - 1) * B_ * H_);
    const float* gi_t = g_gi + (long long)t * B_ * G3;
    float*       out_t = g_outs + (long long)t * B_ * H_;

    // ---- prefetch epilogue operands (latency hidden under GEMM) ----
    float gir[4], giz[4], gin[4], m4[4];
    #pragma unroll
    for (int i = 0; i < 4; i++) {
        int r = m0 + tr * 4 + i;
        gir[i] = __ldg(&gi_t[(long long)r * G3 + j]);
        giz[i] = __ldg(&gi_t[(long long)r * G3 + 512 + j]);
        gin[i] = __ldg(&gi_t[(long long)r * G3 + 1024 + j]);
        m4[i]  = __ldg(&masks[(long long)t * B_ + r]);
    }
    const float br = __ldg(&bhh[j]);
    const float bz = __ldg(&bhh[512 + j]);
    const float bn = __ldg(&bhh[1024 + j]);

    // ---- staging (cp.async, natural layouts) ----
    auto stage = [&](int ci, int sb) {
        const int kb = ci * BK;
        unsigned baseA = smaddr(&As[sb][0]);
        unsigned baseB = smaddr(&Bs[sb][0]);
        // A: 64 rows x 32 k = 512 x 16B, 2 per thread
        #pragma unroll
        for (int q = 0; q < 2; q++) {
            int idx = q * 256 + tid;
            int row = idx >> 3, kc = idx & 7;
            cpasync16(baseA + (unsigned)(row * PADK + kc * 4) * 4,
                      prev + (long long)(m0 + row) * 512 + kb + kc * 4);
        }
        // B: 48 rows x 32 k = 384 x 16B
        {
            int c = tid >> 3, kc = tid & 7;
            int g = c >> 4, jj = c & 15;
            cpasync16(baseB + (unsigned)(c * PADK + kc * 4) * 4,
                      Whh + (long long)((g << 9) + j0 + jj) * 512 + kb + kc * 4);
            if (tid < 128) {
                int idx = 256 + tid;
                c = idx >> 3; kc = idx & 7; g = c >> 4; jj = c & 15;
                cpasync16(baseB + (unsigned)(c * PADK + kc * 4) * 4,
                          Whh + (long long)((g << 9) + j0 + jj) * 512 + kb + kc * 4);
            }
        }
    };

    ull acc[4][3];
    #pragma unroll
    for (int i = 0; i < 4; i++)
        #pragma unroll
        for (int g = 0; g < 3; g++) acc[i][g] = 0ull;

    float hjraw[4];                 // h_prev at this thread's j (unmasked)
    const int cj = j0 >> 5;         // chunk containing columns [j0, j0+16)

    stage(0, 0); cp_commit();

    for (int ci = 0; ci < 16; ci++) {
        const int sb = ci & 1;
        if (ci < 15) { stage(ci + 1, sb ^ 1); cp_commit(); cp_wait<1>(); }
        else         { cp_wait<0>(); }
        __syncthreads();

        const ulonglong2* A2 = (const ulonglong2*)&As[sb][0];
        const ulonglong2* B2 = (const ulonglong2*)&Bs[sb][0];
        #pragma unroll
        for (int k4 = 0; k4 < 8; k4++) {
            ulonglong2 bu0 = B2[(0 * 16 + tc) * (PADK / 4) + k4];
            ulonglong2 bu1 = B2[(1 * 16 + tc) * (PADK / 4) + k4];
            ulonglong2 bu2 = B2[(2 * 16 + tc) * (PADK / 4) + k4];
            #pragma unroll
            for (int i = 0; i < 4; i++) {
                ulonglong2 au = A2[(tr * 4 + i) * (PADK / 4) + k4];
                ffma2(acc[i][0], au.x, bu0.x); ffma2(acc[i][0], au.y, bu0.y);
                ffma2(acc[i][1], au.x, bu1.x); ffma2(acc[i][1], au.y, bu1.y);
                ffma2(acc[i][2], au.x, bu2.x); ffma2(acc[i][2], au.y, bu2.y);
            }
        }
        if (ci == cj) {
            const int off = (j0 & 31) + tc;
            #pragma unroll
            for (int i = 0; i < 4; i++)
                hjraw[i] = As[sb][(tr * 4 + i) * PADK + off];
        }
        __syncthreads();
    }

    // ---- fused gates epilogue ----
    #pragma unroll
    for (int i = 0; i < 4; i++) {
        int r = m0 + tr * 4 + i;
        float s0, s1, s2, lo, hi;
        upk(acc[i][0], lo, hi); s0 = lo + hi;
        upk(acc[i][1], lo, hi); s1 = lo + hi;
        upk(acc[i][2], lo, hi); s2 = lo + hi;
        const float m = m4[i];
        const float ghr = m * s0 + br;
        const float ghz = m * s1 + bz;
        const float ghn = m * s2 + bn;
        const float rr = 1.0f / (1.0f + __expf(-(gir[i] + ghr)));
        const float zz = 1.0f / (1.0f + __expf(-(giz[i] + ghz)));
        const float xv = gin[i] + rr * ghn;
        const float e2 = __expf(-2.0f * fabsf(xv));
        const float th = (1.0f - e2) / (1.0f + e2);
        const float nn = copysignf(th, xv);
        const float hnew = (1.0f - zz) * nn + zz * (m * hjraw[i]);
        out_t[(long long)r * 512 + j] = hnew;
    }
}

// =============================================================================
// Kernel 3: LayerNorm over g_outs -> y in d_out; also copy hT (raw outs[T-1]).
// =============================================================================
__global__ void __launch_bounds__(256) ln_kernel(
    const float* __restrict__ lnw,
    const float* __restrict__ lnb,
    float* __restrict__ out,
    int write_hT)
{
    const int row  = blockIdx.x * 8 + (threadIdx.x >> 5);
    const int lane = threadIdx.x & 31;
    const float4* p4 = (const float4*)(g_outs + (long long)row * 512);

    float4 v[4];
    float s = 0.0f, sq = 0.0f;
    #pragma unroll
    for (int i = 0; i < 4; i++) {
        v[i] = p4[lane + 32 * i];
        s += v[i].x + v[i].y + v[i].z + v[i].w;
        sq = fmaf(v[i].x, v[i].x, sq);
        sq = fmaf(v[i].y, v[i].y, sq);
        sq = fmaf(v[i].z, v[i].z, sq);
        sq = fmaf(v[i].w, v[i].w, sq);
    }
    #pragma unroll
    for (int off = 16; off > 0; off >>= 1) {
        s  += __shfl_xor_sync(0xFFFFFFFFu, s,  off);
        sq += __shfl_xor_sync(0xFFFFFFFFu, sq, off);
    }
    const float mean = s * (1.0f / 512.0f);
    const float var  = sq * (1.0f / 512.0f) - mean * mean;
    const float rstd = rsqrtf(var + 1e-5f);

    float4* o4 = (float4*)out + (long long)row * 128;
    const float4* w4 = (const float4*)lnw;
    const float4* b4 = (const float4*)lnb;
    const bool isLast = (row >= 255 * 256) && write_hT;
    float4* h4 = (float4*)(out + (long long)T_ * B_ * H_) + (long long)(row - 255 * 256) * 128;

    #pragma unroll
    for (int i = 0; i < 4; i++) {
        int idx = lane + 32 * i;
        float4 w = w4[idx], b = b4[idx];
        float4 y;
        y.x = (v[i].x - mean) * rstd * w.x + b.x;
        y.y = (v[i].y - mean) * rstd * w.y + b.y;
        y.z = (v[i].z - mean) * rstd * w.z + b.z;
        y.w = (v[i].w - mean) * rstd * w.w + b.w;
        o4[idx] = y;
        if (isLast) h4[idx] = v[i];
    }
}

// =============================================================================
extern "C" void kernel_launch(void* const* d_in, const int* in_sizes, int n_in,
                              void* d_out, int out_size)
{
    const float* x     = (const float*)d_in[0];  // (T,B,I)
    const float* rnn   = (const float*)d_in[1];  // (1,B,H)
    const float* masks = (const float*)d_in[2];  // (T,B,1)
    const float* Wih   = (const float*)d_in[3];  // (3H,I)
    const float* Whh   = (const float*)d_in[4];  // (3H,H)
    const float* bih   = (const float*)d_in[5];  // (3H)
    const float* bhh   = (const float*)d_in[6];  // (3H)
    const float* lnw   = (const float*)d_in[7];  // (H)
    const float* lnb   = (const float*)d_in[8];  // (H)
    float* out = (float*)d_out;

    (void)in_sizes; (void)n_in;

    // 1) input projections for all timesteps
    gemm_gi_kernel<<<dim3(12, 512), 256>>>(x, Wih, bih);

    // 2) sequential recurrence
    for (int t = 0; t < T_; t++)
        gru_step_kernel<<<dim3(32, 4), 256>>>(t, rnn, masks, Whh, bhh);

    // 3) LayerNorm + hT copy
    const int write_hT = (out_size >= T_ * B_ * H_ + B_ * H_) ? 1 : 0;
    ln_kernel<<<(T_ * B_) / 8, 256>>>(lnw, lnb, out, write_hT);
}